// round 8
// baseline (speedup 1.0000x reference)
#include <cuda_runtime.h>
#include <cuda_bf16.h>
#include <cstdint>

#define FULL 0xFFFFFFFFu

constexpr int DM   = 64;     // model dim (K)
constexpr int NC   = 128;    // 2 heads * 64 (N)
constexpr int DEG  = 8;
constexpr int TILE = 128;    // nodes per CTA (M tile)

// ---------------- device scratch (no runtime allocation) -------------------
__device__ __align__(16) __nv_bfloat16 g_GT_hi[NC * DM];  // GT[n][k] = G[k][n]
__device__ __align__(16) __nv_bfloat16 g_GT_lo[NC * DM];
__device__ float g_v[NC];

// ---------------- smem layout (dynamic, bytes from base) --------------------
constexpr int STRB   = 144;
constexpr int TBYTES = 128 * STRB;           // 18432
constexpr int SM_V   = 0;                    // 128 floats
constexpr int SM_AHI = 1024;
constexpr int SM_ALO = SM_AHI + TBYTES;      // 19456
constexpr int SM_BHI = SM_ALO + TBYTES;      // 37888
constexpr int SM_BLO = SM_BHI + TBYTES;      // 56320  (A/B end 74752)
// w staging reuses the A/B region after MMA completes:
constexpr int SM_WSH   = 1024;
constexpr int WSTRIDE  = 132;                // floats per w row
constexpr int SM_SC    = SM_WSH + TILE * WSTRIDE * 4;  // 68608 (scores)
constexpr int SC_STR   = 20;                 // floats per score row
constexpr int SMEM_BYTES = SM_SC + TILE * SC_STR * 4;  // 78848

// ---------------- ptx helpers ------------------------------------------------
__device__ __forceinline__ uint32_t smem_u32(const void* p) {
    uint32_t a;
    asm("{ .reg .u64 t; cvta.to.shared.u64 t, %1; cvt.u32.u64 %0, t; }" : "=r"(a) : "l"(p));
    return a;
}
__device__ __forceinline__ void ldsm_x4(uint32_t* r, uint32_t addr) {
    asm volatile("ldmatrix.sync.aligned.m8n8.x4.shared.b16 {%0,%1,%2,%3}, [%4];"
                 : "=r"(r[0]), "=r"(r[1]), "=r"(r[2]), "=r"(r[3]) : "r"(addr));
}
__device__ __forceinline__ void mma16816(float* c, const uint32_t* a, uint32_t b0, uint32_t b1) {
    asm volatile(
        "mma.sync.aligned.m16n8k16.row.col.f32.bf16.bf16.f32 "
        "{%0,%1,%2,%3}, {%4,%5,%6,%7}, {%8,%9}, {%0,%1,%2,%3};"
        : "+f"(c[0]), "+f"(c[1]), "+f"(c[2]), "+f"(c[3])
        : "r"(a[0]), "r"(a[1]), "r"(a[2]), "r"(a[3]), "r"(b0), "r"(b1));
}

// bf16 split helpers
__device__ __forceinline__ uint32_t split2(float a, float b, float& la, float& lb) {
    __nv_bfloat16 ha = __float2bfloat16(a), hb = __float2bfloat16(b);
    la = a - __bfloat162float(ha);
    lb = b - __bfloat162float(hb);
    __nv_bfloat162 p = __halves2bfloat162(ha, hb);
    return *reinterpret_cast<uint32_t*>(&p);
}
__device__ __forceinline__ uint32_t pack2(float a, float b) {
    __nv_bfloat162 p = __floats2bfloat162_rn(a, b);
    return *reinterpret_cast<uint32_t*>(&p);
}

// ---------------------------------------------------------------------------
// Prologue: M_h = A_h^T B_h, emitted transposed as bf16 hi/lo:
//   GT[(h*64+e)][d] = M_h[d][e];  v[h*64+e] = sum_t B_h[t][e]*b[h*192+t].
// ---------------------------------------------------------------------------
__global__ void __launch_bounds__(256) prologue_kernel(const float* __restrict__ W,
                                                       const float* __restrict__ b) {
    const int h  = blockIdx.x >> 3;
    const int d0 = (blockIdx.x & 7) * 8;
    __shared__ float Bs[64][64];
    __shared__ float As[64][8];
    const int tid = threadIdx.x;

    const float4* Wk = (const float4*)(W + (h * 192 + 64) * 64);
    float4* Bs4 = (float4*)Bs;
    for (int i = tid; i < 1024; i += 256) Bs4[i] = Wk[i];
    const float* Wq = W + (h * 192) * 64;
    if (tid < 128) {
        int t = tid >> 1, j = (tid & 1) * 4;
        *(float4*)&As[t][j] = *(const float4*)&Wq[t * 64 + d0 + j];
    }
    __syncthreads();

    const int e  = tid & 63;
    const int dj = tid >> 6;  // 0..3
    float a0 = 0.f, a1 = 0.f;
#pragma unroll 8
    for (int t = 0; t < 64; t++) {
        float bv = Bs[t][e];
        a0 += As[t][dj] * bv;
        a1 += As[t][dj + 4] * bv;
    }
    const int row = h * 64 + e;
    {
        __nv_bfloat16 hi = __float2bfloat16(a0);
        g_GT_hi[row * 64 + d0 + dj] = hi;
        g_GT_lo[row * 64 + d0 + dj] = __float2bfloat16(a0 - __bfloat162float(hi));
    }
    {
        __nv_bfloat16 hi = __float2bfloat16(a1);
        g_GT_hi[row * 64 + d0 + dj + 4] = hi;
        g_GT_lo[row * 64 + d0 + dj + 4] = __float2bfloat16(a1 - __bfloat162float(hi));
    }
    if (d0 == 0 && dj == 0) {
        float s = 0.f;
#pragma unroll 8
        for (int t = 0; t < 64; t++) s += Bs[t][e] * b[h * 192 + t];
        g_v[row] = s;
    }
}

// ---------------------------------------------------------------------------
// Fused kernel, 256 threads / CTA
// ---------------------------------------------------------------------------
__device__ __forceinline__ float dot4(float4 a, float4 b) {
    return a.x * b.x + a.y * b.y + a.z * b.z + a.w * b.w;
}

__global__ void __launch_bounds__(256, 2) fused_kernel(const float* __restrict__ x,
                                                       const int* __restrict__ ei,
                                                       float* __restrict__ out,
                                                       int n, int E) {
    extern __shared__ char smem[];
    const uint32_t sb = smem_u32(smem);
    const int tid  = threadIdx.x;
    const int lane = tid & 31;
    const int wid  = tid >> 5;
    const int rowBase = blockIdx.x * TILE;

    float* vsh = (float*)(smem + SM_V);

    // ---- load B = GT hi/lo ----
    {
        const uint4* gth = (const uint4*)g_GT_hi;
        const uint4* gtl = (const uint4*)g_GT_lo;
        for (int i = tid; i < 1024; i += 256) {
            int r = i >> 3, c = i & 7;
            int off = r * STRB + c * 16;
            *(uint4*)(smem + SM_BHI + off) = gth[i];
            *(uint4*)(smem + SM_BLO + off) = gtl[i];
        }
    }
    // ---- convert x tile into bf16 hi/lo ----
    {
        const float4* x4 = (const float4*)x;
        for (int i = tid; i < 1024; i += 256) {
            int r = i >> 3, c = i & 7;
            int gr = rowBase + r;
            float4 f0 = make_float4(0.f, 0.f, 0.f, 0.f), f1 = f0;
            if (gr < n) { f0 = x4[gr * 16 + c * 2]; f1 = x4[gr * 16 + c * 2 + 1]; }
            float l0, l1, l2, l3, l4, l5, l6, l7;
            uint4 hi, lo;
            hi.x = split2(f0.x, f0.y, l0, l1);
            hi.y = split2(f0.z, f0.w, l2, l3);
            hi.z = split2(f1.x, f1.y, l4, l5);
            hi.w = split2(f1.z, f1.w, l6, l7);
            lo.x = pack2(l0, l1); lo.y = pack2(l2, l3);
            lo.z = pack2(l4, l5); lo.w = pack2(l6, l7);
            int off = r * STRB + c * 16;
            *(uint4*)(smem + SM_AHI + off) = hi;
            *(uint4*)(smem + SM_ALO + off) = lo;
        }
    }
    if (tid < NC) vsh[tid] = g_v[tid];
    __syncthreads();

    // ---- MMA: 2-D warp partition: wr=wid>>1 (32 rows), wc=wid&1 (64 cols) ----
    const int wr = wid >> 1;
    const int wc = wid & 1;
    float acc[16][4];
#pragma unroll
    for (int f = 0; f < 16; f++) { acc[f][0] = acc[f][1] = acc[f][2] = acc[f][3] = 0.f; }

    const uint32_t aOff0 = (uint32_t)((wr * 32 + (lane & 15)) * STRB + ((lane >> 4) << 4));
    const uint32_t aOff1 = aOff0 + 16 * STRB;
    const uint32_t bOffL =
        (uint32_t)(((lane & 7) + ((lane >> 4) << 3)) * STRB + (((lane >> 3) & 1) << 4));

#pragma unroll
    for (int k = 0; k < 4; k++) {
        uint32_t ah0[4], ah1[4], al0[4], al1[4];
        ldsm_x4(ah0, sb + SM_AHI + aOff0 + k * 32);
        ldsm_x4(ah1, sb + SM_AHI + aOff1 + k * 32);
        ldsm_x4(al0, sb + SM_ALO + aOff0 + k * 32);
        ldsm_x4(al1, sb + SM_ALO + aOff1 + k * 32);
#pragma unroll
        for (int nb = 0; nb < 4; nb++) {
            const uint32_t bRow = (uint32_t)((wc * 64 + nb * 16) * STRB) + bOffL + k * 32;
            uint32_t bh[4], bl[4];
            ldsm_x4(bh, sb + SM_BHI + bRow);
            mma16816(acc[nb * 2 + 0], ah0, bh[0], bh[1]);
            mma16816(acc[nb * 2 + 1], ah0, bh[2], bh[3]);
            mma16816(acc[8 + nb * 2 + 0], ah1, bh[0], bh[1]);
            mma16816(acc[8 + nb * 2 + 1], ah1, bh[2], bh[3]);
            mma16816(acc[nb * 2 + 0], al0, bh[0], bh[1]);
            mma16816(acc[nb * 2 + 1], al0, bh[2], bh[3]);
            mma16816(acc[8 + nb * 2 + 0], al1, bh[0], bh[1]);
            mma16816(acc[8 + nb * 2 + 1], al1, bh[2], bh[3]);
            ldsm_x4(bl, sb + SM_BLO + bRow);
            mma16816(acc[nb * 2 + 0], ah0, bl[0], bl[1]);
            mma16816(acc[nb * 2 + 1], ah0, bl[2], bl[3]);
            mma16816(acc[8 + nb * 2 + 0], ah1, bl[0], bl[1]);
            mma16816(acc[8 + nb * 2 + 1], ah1, bl[2], bl[3]);
        }
    }

    __syncthreads();  // all MMA smem reads done; safe to overlay w

    // ---- epilogue: w = D + v into smem ----
    float* wsh = (float*)(smem + SM_WSH);
    {
        const int g = lane >> 2, tig = lane & 3;
#pragma unroll
        for (int rb = 0; rb < 2; rb++) {
            const int row0 = wr * 32 + rb * 16 + g;
#pragma unroll
            for (int nb = 0; nb < 4; nb++) {
#pragma unroll
                for (int j = 0; j < 2; j++) {
                    const int col = wc * 64 + nb * 16 + j * 8 + 2 * tig;
                    const float* a = acc[rb * 8 + nb * 2 + j];
                    float v0 = vsh[col], v1 = vsh[col + 1];
                    *(float2*)&wsh[row0 * WSTRIDE + col] = make_float2(a[0] + v0, a[1] + v1);
                    *(float2*)&wsh[(row0 + 8) * WSTRIDE + col] = make_float2(a[2] + v0, a[3] + v1);
                }
            }
        }
    }
    __syncthreads();  // w fully written (rows span warps)

    // ---- score phase v2: warp -> 16 nodes, 2 nodes per iteration.
    //      lane = (p, g, t): p=node-in-pair (lane>>4), g=neighbor ((lane>>1)&7),
    //      t=half (lane&1). Lane computes a 32-dim partial of BOTH heads using
    //      interleaved float4 indices (2i+t) -> LDG pairs are 32B-contiguous
    //      (full sectors); w side uses the same permutation. One shfl per head.
    float* sc = (float*)(smem + SM_SC);
    const int* cols = ei + E;
    const int r0 = wid * 16;
    const int nW = min(16, n - (rowBase + r0));

    if (nW > 0) {
        const int p = lane >> 4;
        const int g = (lane >> 1) & 7;
        const int t = lane & 1;
        const int* colp = cols + (size_t)(rowBase + r0) * DEG + g;
        const int nPairs = (nW + 1) >> 1;

        float4 xq[8];
        {
            int idx0 = p;  // node offset 2*0+p
            int c = (idx0 < nW) ? colp[idx0 * DEG] : colp[0];
            const float4* xp = (const float4*)(x + (size_t)c * DM);
#pragma unroll
            for (int i = 0; i < 8; i++) xq[i] = xp[2 * i + t];
        }

#pragma unroll 2
        for (int it = 0; it < nPairs; it++) {
            float4 cx[8];
#pragma unroll
            for (int i = 0; i < 8; i++) cx[i] = xq[i];
            if (it + 1 < nPairs) {  // prefetch next pair's row
                int idxn = 2 * (it + 1) + p;
                int cn = (idxn < nW) ? colp[idxn * DEG] : colp[0];
                const float4* xn = (const float4*)(x + (size_t)cn * DM);
#pragma unroll
                for (int i = 0; i < 8; i++) xq[i] = xn[2 * i + t];
            }

            const int idx = 2 * it + p;
            const int r = r0 + idx;
            const float4* wr4 = (const float4*)(wsh + r * WSTRIDE);

            float a0 = 0.f, b0 = 0.f, a1 = 0.f, b1 = 0.f;
#pragma unroll
            for (int i = 0; i < 8; i += 2) {
                a0 += dot4(wr4[2 * i + t], cx[i]);
                b0 += dot4(wr4[2 * (i + 1) + t], cx[i + 1]);
                a1 += dot4(wr4[16 + 2 * i + t], cx[i]);
                b1 += dot4(wr4[16 + 2 * (i + 1) + t], cx[i + 1]);
            }
            float p0 = a0 + b0;
            float p1 = a1 + b1;

            p0 += __shfl_xor_sync(FULL, p0, 1);
            p1 += __shfl_xor_sync(FULL, p1, 1);

            if (t == 0 && idx < nW) {
                sc[r * SC_STR + g] = p0 * 8.0f;
                sc[r * SC_STR + 8 + g] = p1 * 8.0f;
            }
        }
    }
    __syncwarp();

    // ---- softmax phase: lane = node (lanes 0..15), zero shuffles ----
    if (lane < nW) {
        const int r = r0 + lane;
        const int node = rowBase + r;
        const float* srow = sc + r * SC_STR;
        float4 sa = *(const float4*)(srow + 0);
        float4 sb4 = *(const float4*)(srow + 4);
        float4 ta = *(const float4*)(srow + 8);
        float4 tb = *(const float4*)(srow + 12);

        float m0 = fmaxf(fmaxf(fmaxf(sa.x, sa.y), fmaxf(sa.z, sa.w)),
                         fmaxf(fmaxf(sb4.x, sb4.y), fmaxf(sb4.z, sb4.w)));
        float m1 = fmaxf(fmaxf(fmaxf(ta.x, ta.y), fmaxf(ta.z, ta.w)),
                         fmaxf(fmaxf(tb.x, tb.y), fmaxf(tb.z, tb.w)));

        float e0[8], e1[8];
        e0[0] = __expf(sa.x - m0); e0[1] = __expf(sa.y - m0);
        e0[2] = __expf(sa.z - m0); e0[3] = __expf(sa.w - m0);
        e0[4] = __expf(sb4.x - m0); e0[5] = __expf(sb4.y - m0);
        e0[6] = __expf(sb4.z - m0); e0[7] = __expf(sb4.w - m0);
        e1[0] = __expf(ta.x - m1); e1[1] = __expf(ta.y - m1);
        e1[2] = __expf(ta.z - m1); e1[3] = __expf(ta.w - m1);
        e1[4] = __expf(tb.x - m1); e1[5] = __expf(tb.y - m1);
        e1[6] = __expf(tb.z - m1); e1[7] = __expf(tb.w - m1);

        float z0 = (e0[0] + e0[1]) + (e0[2] + e0[3]) + (e0[4] + e0[5]) + (e0[6] + e0[7]);
        float z1 = (e1[0] + e1[1]) + (e1[2] + e1[3]) + (e1[4] + e1[5]) + (e1[6] + e1[7]);
        float i0 = 0.5f / z0, i1 = 0.5f / z1;

        float4 o0 = make_float4(e0[0] * i0 + e1[0] * i1, e0[1] * i0 + e1[1] * i1,
                                e0[2] * i0 + e1[2] * i1, e0[3] * i0 + e1[3] * i1);
        float4 o1 = make_float4(e0[4] * i0 + e1[4] * i1, e0[5] * i0 + e1[5] * i1,
                                e0[6] * i0 + e1[6] * i1, e0[7] * i0 + e1[7] * i1);
        float4* op = (float4*)(out + (size_t)node * DEG);
        op[0] = o0;
        op[1] = o1;
    }
}

// ---------------------------------------------------------------------------
extern "C" void kernel_launch(void* const* d_in, const int* in_sizes, int n_in,
                              void* d_out, int out_size) {
    const float* x = (const float*)d_in[0];
    const float* W = (const float*)d_in[1];
    const float* b = (const float*)d_in[2];
    const int* ei  = (const int*)d_in[3];
    float* out = (float*)d_out;

    const int n = in_sizes[0] / DM;
    const int E = in_sizes[3] / 2;

    static bool attr_set = false;
    if (!attr_set) {
        cudaFuncSetAttribute(fused_kernel, cudaFuncAttributeMaxDynamicSharedMemorySize, SMEM_BYTES);
        attr_set = true;
    }

    prologue_kernel<<<16, 256>>>(W, b);
    fused_kernel<<<(n + TILE - 1) / TILE, 256, SMEM_BYTES>>>(x, ei, out, n, E);
}

// round 9
// speedup vs baseline: 1.0098x; 1.0098x over previous
#include <cuda_runtime.h>
#include <cuda_bf16.h>
#include <cstdint>

#define FULL 0xFFFFFFFFu

constexpr int DM   = 64;     // model dim (K)
constexpr int NC   = 128;    // 2 heads * 64 (N)
constexpr int DEG  = 8;
constexpr int TILE = 128;    // nodes per CTA (M tile)

// ---------------- device scratch (no runtime allocation) -------------------
__device__ __align__(16) __nv_bfloat16 g_GT_hi[NC * DM];  // GT[n][k] = G[k][n]
__device__ __align__(16) __nv_bfloat16 g_GT_lo[NC * DM];
__device__ float g_v[NC];

// ---------------- smem layout (dynamic, bytes from base) --------------------
constexpr int STRB   = 144;
constexpr int TBYTES = 128 * STRB;           // 18432
constexpr int SM_V   = 0;                    // 128 floats
constexpr int SM_AHI = 1024;
constexpr int SM_ALO = SM_AHI + TBYTES;      // 19456
constexpr int SM_BHI = SM_ALO + TBYTES;      // 37888
constexpr int SM_BLO = SM_BHI + TBYTES;      // 56320
constexpr int SMEM_BYTES = SM_BLO + TBYTES;  // 74752
// w staging reuses the A/B region after MMA completes:
constexpr int SM_WSH   = 1024;
constexpr int WSTRIDE  = 132;                // floats per w row (ends at 68608)

// ---------------- ptx helpers ------------------------------------------------
__device__ __forceinline__ uint32_t smem_u32(const void* p) {
    uint32_t a;
    asm("{ .reg .u64 t; cvta.to.shared.u64 t, %1; cvt.u32.u64 %0, t; }" : "=r"(a) : "l"(p));
    return a;
}
__device__ __forceinline__ void ldsm_x4(uint32_t* r, uint32_t addr) {
    asm volatile("ldmatrix.sync.aligned.m8n8.x4.shared.b16 {%0,%1,%2,%3}, [%4];"
                 : "=r"(r[0]), "=r"(r[1]), "=r"(r[2]), "=r"(r[3]) : "r"(addr));
}
__device__ __forceinline__ void mma16816(float* c, const uint32_t* a, uint32_t b0, uint32_t b1) {
    asm volatile(
        "mma.sync.aligned.m16n8k16.row.col.f32.bf16.bf16.f32 "
        "{%0,%1,%2,%3}, {%4,%5,%6,%7}, {%8,%9}, {%0,%1,%2,%3};"
        : "+f"(c[0]), "+f"(c[1]), "+f"(c[2]), "+f"(c[3])
        : "r"(a[0]), "r"(a[1]), "r"(a[2]), "r"(a[3]), "r"(b0), "r"(b1));
}

// bf16 split helpers
__device__ __forceinline__ uint32_t split2(float a, float b, float& la, float& lb) {
    __nv_bfloat16 ha = __float2bfloat16(a), hb = __float2bfloat16(b);
    la = a - __bfloat162float(ha);
    lb = b - __bfloat162float(hb);
    __nv_bfloat162 p = __halves2bfloat162(ha, hb);
    return *reinterpret_cast<uint32_t*>(&p);
}
__device__ __forceinline__ uint32_t pack2(float a, float b) {
    __nv_bfloat162 p = __floats2bfloat162_rn(a, b);
    return *reinterpret_cast<uint32_t*>(&p);
}

// pick element 2t (resp. 2t+1) of 8 register values without dynamic indexing
__device__ __forceinline__ float sel4(float v0, float v1, float v2, float v3, int t) {
    float lo = (t & 1) ? v1 : v0;
    float hi = (t & 1) ? v3 : v2;
    return (t & 2) ? hi : lo;
}

// ---------------------------------------------------------------------------
// Prologue: M_h = A_h^T B_h, emitted transposed as bf16 hi/lo:
//   GT[(h*64+e)][d] = M_h[d][e];  v[h*64+e] = sum_t B_h[t][e]*b[h*192+t].
// ---------------------------------------------------------------------------
__global__ void __launch_bounds__(256) prologue_kernel(const float* __restrict__ W,
                                                       const float* __restrict__ b) {
    const int h  = blockIdx.x >> 3;
    const int d0 = (blockIdx.x & 7) * 8;
    __shared__ float Bs[64][64];
    __shared__ float As[64][8];
    const int tid = threadIdx.x;

    const float4* Wk = (const float4*)(W + (h * 192 + 64) * 64);
    float4* Bs4 = (float4*)Bs;
    for (int i = tid; i < 1024; i += 256) Bs4[i] = Wk[i];
    const float* Wq = W + (h * 192) * 64;
    if (tid < 128) {
        int t = tid >> 1, j = (tid & 1) * 4;
        *(float4*)&As[t][j] = *(const float4*)&Wq[t * 64 + d0 + j];
    }
    __syncthreads();

    const int e  = tid & 63;
    const int dj = tid >> 6;  // 0..3
    float a0 = 0.f, a1 = 0.f;
#pragma unroll 8
    for (int t = 0; t < 64; t++) {
        float bv = Bs[t][e];
        a0 += As[t][dj] * bv;
        a1 += As[t][dj + 4] * bv;
    }
    const int row = h * 64 + e;
    {
        __nv_bfloat16 hi = __float2bfloat16(a0);
        g_GT_hi[row * 64 + d0 + dj] = hi;
        g_GT_lo[row * 64 + d0 + dj] = __float2bfloat16(a0 - __bfloat162float(hi));
    }
    {
        __nv_bfloat16 hi = __float2bfloat16(a1);
        g_GT_hi[row * 64 + d0 + dj + 4] = hi;
        g_GT_lo[row * 64 + d0 + dj + 4] = __float2bfloat16(a1 - __bfloat162float(hi));
    }
    if (d0 == 0 && dj == 0) {
        float s = 0.f;
#pragma unroll 8
        for (int t = 0; t < 64; t++) s += Bs[t][e] * b[h * 192 + t];
        g_v[row] = s;
    }
}

// ---------------------------------------------------------------------------
// Fused kernel, 256 threads / CTA
// ---------------------------------------------------------------------------
__device__ __forceinline__ float dot4(float4 a, float4 b) {
    return a.x * b.x + a.y * b.y + a.z * b.z + a.w * b.w;
}

__global__ void __launch_bounds__(256, 2) fused_kernel(const float* __restrict__ x,
                                                       const int* __restrict__ ei,
                                                       float* __restrict__ out,
                                                       int n, int E) {
    extern __shared__ char smem[];
    const uint32_t sb = smem_u32(smem);
    const int tid  = threadIdx.x;
    const int lane = tid & 31;
    const int wid  = tid >> 5;
    const int rowBase = blockIdx.x * TILE;

    float* vsh = (float*)(smem + SM_V);

    // ---- load B = GT hi/lo ----
    {
        const uint4* gth = (const uint4*)g_GT_hi;
        const uint4* gtl = (const uint4*)g_GT_lo;
        for (int i = tid; i < 1024; i += 256) {
            int r = i >> 3, c = i & 7;
            int off = r * STRB + c * 16;
            *(uint4*)(smem + SM_BHI + off) = gth[i];
            *(uint4*)(smem + SM_BLO + off) = gtl[i];
        }
    }
    // ---- convert x tile into bf16 hi/lo ----
    {
        const float4* x4 = (const float4*)x;
        for (int i = tid; i < 1024; i += 256) {
            int r = i >> 3, c = i & 7;
            int gr = rowBase + r;
            float4 f0 = make_float4(0.f, 0.f, 0.f, 0.f), f1 = f0;
            if (gr < n) { f0 = x4[gr * 16 + c * 2]; f1 = x4[gr * 16 + c * 2 + 1]; }
            float l0, l1, l2, l3, l4, l5, l6, l7;
            uint4 hi, lo;
            hi.x = split2(f0.x, f0.y, l0, l1);
            hi.y = split2(f0.z, f0.w, l2, l3);
            hi.z = split2(f1.x, f1.y, l4, l5);
            hi.w = split2(f1.z, f1.w, l6, l7);
            lo.x = pack2(l0, l1); lo.y = pack2(l2, l3);
            lo.z = pack2(l4, l5); lo.w = pack2(l6, l7);
            int off = r * STRB + c * 16;
            *(uint4*)(smem + SM_AHI + off) = hi;
            *(uint4*)(smem + SM_ALO + off) = lo;
        }
    }
    if (tid < NC) vsh[tid] = g_v[tid];
    __syncthreads();

    // ---- MMA: 2-D warp partition: wr=wid>>1 (32 rows), wc=wid&1 (64 cols) ----
    const int wr = wid >> 1;
    const int wc = wid & 1;
    float acc[16][4];
#pragma unroll
    for (int f = 0; f < 16; f++) { acc[f][0] = acc[f][1] = acc[f][2] = acc[f][3] = 0.f; }

    const uint32_t aOff0 = (uint32_t)((wr * 32 + (lane & 15)) * STRB + ((lane >> 4) << 4));
    const uint32_t aOff1 = aOff0 + 16 * STRB;
    const uint32_t bOffL =
        (uint32_t)(((lane & 7) + ((lane >> 4) << 3)) * STRB + (((lane >> 3) & 1) << 4));

#pragma unroll
    for (int k = 0; k < 4; k++) {
        uint32_t ah0[4], ah1[4], al0[4], al1[4];
        ldsm_x4(ah0, sb + SM_AHI + aOff0 + k * 32);
        ldsm_x4(ah1, sb + SM_AHI + aOff1 + k * 32);
        ldsm_x4(al0, sb + SM_ALO + aOff0 + k * 32);
        ldsm_x4(al1, sb + SM_ALO + aOff1 + k * 32);
#pragma unroll
        for (int nb = 0; nb < 4; nb++) {
            const uint32_t bRow = (uint32_t)((wc * 64 + nb * 16) * STRB) + bOffL + k * 32;
            uint32_t bh[4], bl[4];
            ldsm_x4(bh, sb + SM_BHI + bRow);
            mma16816(acc[nb * 2 + 0], ah0, bh[0], bh[1]);
            mma16816(acc[nb * 2 + 1], ah0, bh[2], bh[3]);
            mma16816(acc[8 + nb * 2 + 0], ah1, bh[0], bh[1]);
            mma16816(acc[8 + nb * 2 + 1], ah1, bh[2], bh[3]);
            mma16816(acc[nb * 2 + 0], al0, bh[0], bh[1]);
            mma16816(acc[nb * 2 + 1], al0, bh[2], bh[3]);
            mma16816(acc[8 + nb * 2 + 0], al1, bh[0], bh[1]);
            mma16816(acc[8 + nb * 2 + 1], al1, bh[2], bh[3]);
            ldsm_x4(bl, sb + SM_BLO + bRow);
            mma16816(acc[nb * 2 + 0], ah0, bl[0], bl[1]);
            mma16816(acc[nb * 2 + 1], ah0, bl[2], bl[3]);
            mma16816(acc[8 + nb * 2 + 0], ah1, bl[0], bl[1]);
            mma16816(acc[8 + nb * 2 + 1], ah1, bl[2], bl[3]);
        }
    }

    __syncthreads();  // all MMA smem reads done; safe to overlay w

    // ---- epilogue: w = D + v into smem ----
    float* wsh = (float*)(smem + SM_WSH);
    {
        const int g = lane >> 2, tig = lane & 3;
#pragma unroll
        for (int rb = 0; rb < 2; rb++) {
            const int row0 = wr * 32 + rb * 16 + g;
#pragma unroll
            for (int nb = 0; nb < 4; nb++) {
#pragma unroll
                for (int j = 0; j < 2; j++) {
                    const int col = wc * 64 + nb * 16 + j * 8 + 2 * tig;
                    const float* a = acc[rb * 8 + nb * 2 + j];
                    float v0 = vsh[col], v1 = vsh[col + 1];
                    *(float2*)&wsh[row0 * WSTRIDE + col] = make_float2(a[0] + v0, a[1] + v1);
                    *(float2*)&wsh[(row0 + 8) * WSTRIDE + col] = make_float2(a[2] + v0, a[3] + v1);
                }
            }
        }
    }
    __syncthreads();  // w fully written (rows span warps)

    // ---- score+softmax v3: warp -> 16 nodes in two groups of 8.
    //      lane = (q=node-in-group lane>>2, t=quarter lane&3). w chunks for the
    //      node live in REGISTERS (loaded once, 512B/node total from smem);
    //      the 8 neighbors are processed sequentially reusing them. After the
    //      xor-reduce every lane holds the full scores -> softmax in registers,
    //      no score buffer, no extra phase. ----
    const int* cols = ei + E;
    const int r0 = wid * 16;
    const int q = lane >> 2;
    const int t = lane & 3;

#pragma unroll
    for (int h = 0; h < 2; h++) {
        const int r = r0 + h * 8 + q;
        const int node = rowBase + r;
        const bool active = node < n;

        // w chunks: head0 dims [16t,16t+16), head1 same
        const float4* wr4 = (const float4*)(wsh + r * WSTRIDE);
        float4 w0[4], w1[4];
#pragma unroll
        for (int i = 0; i < 4; i++) {
            w0[i] = wr4[4 * t + i];
            w1[i] = wr4[16 + 4 * t + i];
        }

        int cj[8];
        if (active) {
            const int4* cp = (const int4*)(cols + (size_t)node * DEG);
            int4 ca = cp[0], cb = cp[1];
            cj[0] = ca.x; cj[1] = ca.y; cj[2] = ca.z; cj[3] = ca.w;
            cj[4] = cb.x; cj[5] = cb.y; cj[6] = cb.z; cj[7] = cb.w;
        } else {
#pragma unroll
            for (int j = 0; j < 8; j++) cj[j] = 0;
        }

        // depth-2 prefetch: lane reads 64B contiguous (full sectors)
        float4 xA[4], xB[4];
        {
            const float4* xp = (const float4*)(x + (size_t)cj[0] * DM);
#pragma unroll
            for (int i = 0; i < 4; i++) xA[i] = xp[4 * t + i];
            const float4* xq = (const float4*)(x + (size_t)cj[1] * DM);
#pragma unroll
            for (int i = 0; i < 4; i++) xB[i] = xq[4 * t + i];
        }

        float s0[8], s1[8];
#pragma unroll
        for (int j = 0; j < 8; j++) {
            float4 c0, c1, c2, c3;
            if ((j & 1) == 0) { c0 = xA[0]; c1 = xA[1]; c2 = xA[2]; c3 = xA[3]; }
            else              { c0 = xB[0]; c1 = xB[1]; c2 = xB[2]; c3 = xB[3]; }
            if (j + 2 < 8) {
                const float4* xn = (const float4*)(x + (size_t)cj[j + 2] * DM);
                if ((j & 1) == 0) {
#pragma unroll
                    for (int i = 0; i < 4; i++) xA[i] = xn[4 * t + i];
                } else {
#pragma unroll
                    for (int i = 0; i < 4; i++) xB[i] = xn[4 * t + i];
                }
            }
            float p0 = (dot4(w0[0], c0) + dot4(w0[1], c1)) + (dot4(w0[2], c2) + dot4(w0[3], c3));
            float p1 = (dot4(w1[0], c0) + dot4(w1[1], c1)) + (dot4(w1[2], c2) + dot4(w1[3], c3));
            p0 += __shfl_xor_sync(FULL, p0, 1);
            p0 += __shfl_xor_sync(FULL, p0, 2);
            p1 += __shfl_xor_sync(FULL, p1, 1);
            p1 += __shfl_xor_sync(FULL, p1, 2);
            s0[j] = p0 * 8.0f;
            s1[j] = p1 * 8.0f;
        }

        // softmax in registers (all 4 lanes of the group hold identical s)
        float m0 = fmaxf(fmaxf(fmaxf(s0[0], s0[1]), fmaxf(s0[2], s0[3])),
                         fmaxf(fmaxf(s0[4], s0[5]), fmaxf(s0[6], s0[7])));
        float m1 = fmaxf(fmaxf(fmaxf(s1[0], s1[1]), fmaxf(s1[2], s1[3])),
                         fmaxf(fmaxf(s1[4], s1[5]), fmaxf(s1[6], s1[7])));
        float e0[8], e1[8];
#pragma unroll
        for (int j = 0; j < 8; j++) {
            e0[j] = __expf(s0[j] - m0);
            e1[j] = __expf(s1[j] - m1);
        }
        float z0 = (e0[0] + e0[1]) + (e0[2] + e0[3]) + (e0[4] + e0[5]) + (e0[6] + e0[7]);
        float z1 = (e1[0] + e1[1]) + (e1[2] + e1[3]) + (e1[4] + e1[5]) + (e1[6] + e1[7]);
        float i0 = 0.5f / z0, i1 = 0.5f / z1;

        // lane t writes outputs 2t, 2t+1 (compile-time-free selects)
        float a0 = sel4(e0[0], e0[2], e0[4], e0[6], t);
        float a1 = sel4(e0[1], e0[3], e0[5], e0[7], t);
        float b0 = sel4(e1[0], e1[2], e1[4], e1[6], t);
        float b1 = sel4(e1[1], e1[3], e1[5], e1[7], t);
        if (active) {
            float2 o = make_float2(a0 * i0 + b0 * i1, a1 * i0 + b1 * i1);
            ((float2*)(out + (size_t)node * DEG))[t] = o;
        }
    }
}

// ---------------------------------------------------------------------------
extern "C" void kernel_launch(void* const* d_in, const int* in_sizes, int n_in,
                              void* d_out, int out_size) {
    const float* x = (const float*)d_in[0];
    const float* W = (const float*)d_in[1];
    const float* b = (const float*)d_in[2];
    const int* ei  = (const int*)d_in[3];
    float* out = (float*)d_out;

    const int n = in_sizes[0] / DM;
    const int E = in_sizes[3] / 2;

    static bool attr_set = false;
    if (!attr_set) {
        cudaFuncSetAttribute(fused_kernel, cudaFuncAttributeMaxDynamicSharedMemorySize, SMEM_BYTES);
        attr_set = true;
    }

    prologue_kernel<<<16, 256>>>(W, b);
    fused_kernel<<<(n + TILE - 1) / TILE, 256, SMEM_BYTES>>>(x, ei, out, n, E);
}

// round 11
// speedup vs baseline: 1.2592x; 1.2469x over previous
#include <cuda_runtime.h>
#include <cuda_bf16.h>
#include <cstdint>

#define FULL 0xFFFFFFFFu

constexpr int DM   = 64;     // model dim (K)
constexpr int NC   = 128;    // 2 heads * 64 (N)
constexpr int DEG  = 8;
constexpr int TILE = 128;    // nodes per CTA (M tile)

// ---------------- device scratch (no runtime allocation) -------------------
__device__ __align__(16) __nv_bfloat16 g_GT_hi[NC * DM];  // GT[n][k] = G[k][n]
__device__ __align__(16) __nv_bfloat16 g_GT_lo[NC * DM];
__device__ float g_v[NC];

// ---------------- smem layout (dynamic, bytes from base) --------------------
constexpr int STRB   = 144;
constexpr int TBYTES = 128 * STRB;           // 18432
constexpr int SM_V   = 0;                    // 128 floats
constexpr int SM_AHI = 1024;
constexpr int SM_ALO = SM_AHI + TBYTES;      // 19456
constexpr int SM_BHI = SM_ALO + TBYTES;      // 37888
constexpr int SM_BLO = SM_BHI + TBYTES;      // 56320
constexpr int SMEM_BYTES = SM_BLO + TBYTES;  // 74752
// w staging reuses the A/B region after MMA completes:
constexpr int SM_WSH   = 1024;
constexpr int WSTRIDE  = 132;                // floats per w row (ends at 68608)

// ---------------- ptx helpers ------------------------------------------------
__device__ __forceinline__ uint32_t smem_u32(const void* p) {
    uint32_t a;
    asm("{ .reg .u64 t; cvta.to.shared.u64 t, %1; cvt.u32.u64 %0, t; }" : "=r"(a) : "l"(p));
    return a;
}
__device__ __forceinline__ void ldsm_x4(uint32_t* r, uint32_t addr) {
    asm volatile("ldmatrix.sync.aligned.m8n8.x4.shared.b16 {%0,%1,%2,%3}, [%4];"
                 : "=r"(r[0]), "=r"(r[1]), "=r"(r[2]), "=r"(r[3]) : "r"(addr));
}
__device__ __forceinline__ void mma16816(float* c, const uint32_t* a, uint32_t b0, uint32_t b1) {
    asm volatile(
        "mma.sync.aligned.m16n8k16.row.col.f32.bf16.bf16.f32 "
        "{%0,%1,%2,%3}, {%4,%5,%6,%7}, {%8,%9}, {%0,%1,%2,%3};"
        : "+f"(c[0]), "+f"(c[1]), "+f"(c[2]), "+f"(c[3])
        : "r"(a[0]), "r"(a[1]), "r"(a[2]), "r"(a[3]), "r"(b0), "r"(b1));
}

// bf16 split helpers
__device__ __forceinline__ uint32_t split2(float a, float b, float& la, float& lb) {
    __nv_bfloat16 ha = __float2bfloat16(a), hb = __float2bfloat16(b);
    la = a - __bfloat162float(ha);
    lb = b - __bfloat162float(hb);
    __nv_bfloat162 p = __halves2bfloat162(ha, hb);
    return *reinterpret_cast<uint32_t*>(&p);
}
__device__ __forceinline__ uint32_t pack2(float a, float b) {
    __nv_bfloat162 p = __floats2bfloat162_rn(a, b);
    return *reinterpret_cast<uint32_t*>(&p);
}

// pick element 2t (resp. 2t+1) of 8 register values without dynamic indexing
__device__ __forceinline__ float sel4(float v0, float v1, float v2, float v3, int t) {
    float lo = (t & 1) ? v1 : v0;
    float hi = (t & 1) ? v3 : v2;
    return (t & 2) ? hi : lo;
}

// ---------------------------------------------------------------------------
// Prologue: M_h = A_h^T B_h, emitted transposed as bf16 hi/lo:
//   GT[(h*64+e)][d] = M_h[d][e];  v[h*64+e] = sum_t B_h[t][e]*b[h*192+t].
// ---------------------------------------------------------------------------
__global__ void __launch_bounds__(256) prologue_kernel(const float* __restrict__ W,
                                                       const float* __restrict__ b) {
    const int h  = blockIdx.x >> 3;
    const int d0 = (blockIdx.x & 7) * 8;
    __shared__ float Bs[64][64];
    __shared__ float As[64][8];
    const int tid = threadIdx.x;

    const float4* Wk = (const float4*)(W + (h * 192 + 64) * 64);
    float4* Bs4 = (float4*)Bs;
    for (int i = tid; i < 1024; i += 256) Bs4[i] = Wk[i];
    const float* Wq = W + (h * 192) * 64;
    if (tid < 128) {
        int t = tid >> 1, j = (tid & 1) * 4;
        *(float4*)&As[t][j] = *(const float4*)&Wq[t * 64 + d0 + j];
    }
    __syncthreads();

    const int e  = tid & 63;
    const int dj = tid >> 6;  // 0..3
    float a0 = 0.f, a1 = 0.f;
#pragma unroll 8
    for (int t = 0; t < 64; t++) {
        float bv = Bs[t][e];
        a0 += As[t][dj] * bv;
        a1 += As[t][dj + 4] * bv;
    }
    const int row = h * 64 + e;
    {
        __nv_bfloat16 hi = __float2bfloat16(a0);
        g_GT_hi[row * 64 + d0 + dj] = hi;
        g_GT_lo[row * 64 + d0 + dj] = __float2bfloat16(a0 - __bfloat162float(hi));
    }
    {
        __nv_bfloat16 hi = __float2bfloat16(a1);
        g_GT_hi[row * 64 + d0 + dj + 4] = hi;
        g_GT_lo[row * 64 + d0 + dj + 4] = __float2bfloat16(a1 - __bfloat162float(hi));
    }
    if (d0 == 0 && dj == 0) {
        float s = 0.f;
#pragma unroll 8
        for (int t = 0; t < 64; t++) s += Bs[t][e] * b[h * 192 + t];
        g_v[row] = s;
    }
}

// ---------------------------------------------------------------------------
// Fused kernel, 256 threads / CTA
// ---------------------------------------------------------------------------
__device__ __forceinline__ float dot4(float4 a, float4 b) {
    return a.x * b.x + a.y * b.y + a.z * b.z + a.w * b.w;
}

__global__ void __launch_bounds__(256, 2) fused_kernel(const float* __restrict__ x,
                                                       const int* __restrict__ ei,
                                                       float* __restrict__ out,
                                                       int n, int E) {
    extern __shared__ char smem[];
    const uint32_t sb = smem_u32(smem);
    const int tid  = threadIdx.x;
    const int lane = tid & 31;
    const int wid  = tid >> 5;
    const int rowBase = blockIdx.x * TILE;

    float* vsh = (float*)(smem + SM_V);

    // ---- load B = GT hi/lo ----
    {
        const uint4* gth = (const uint4*)g_GT_hi;
        const uint4* gtl = (const uint4*)g_GT_lo;
        for (int i = tid; i < 1024; i += 256) {
            int r = i >> 3, c = i & 7;
            int off = r * STRB + c * 16;
            *(uint4*)(smem + SM_BHI + off) = gth[i];
            *(uint4*)(smem + SM_BLO + off) = gtl[i];
        }
    }
    // ---- convert x tile into bf16 hi/lo ----
    {
        const float4* x4 = (const float4*)x;
        for (int i = tid; i < 1024; i += 256) {
            int r = i >> 3, c = i & 7;
            int gr = rowBase + r;
            float4 f0 = make_float4(0.f, 0.f, 0.f, 0.f), f1 = f0;
            if (gr < n) { f0 = x4[gr * 16 + c * 2]; f1 = x4[gr * 16 + c * 2 + 1]; }
            float l0, l1, l2, l3, l4, l5, l6, l7;
            uint4 hi, lo;
            hi.x = split2(f0.x, f0.y, l0, l1);
            hi.y = split2(f0.z, f0.w, l2, l3);
            hi.z = split2(f1.x, f1.y, l4, l5);
            hi.w = split2(f1.z, f1.w, l6, l7);
            lo.x = pack2(l0, l1); lo.y = pack2(l2, l3);
            lo.z = pack2(l4, l5); lo.w = pack2(l6, l7);
            int off = r * STRB + c * 16;
            *(uint4*)(smem + SM_AHI + off) = hi;
            *(uint4*)(smem + SM_ALO + off) = lo;
        }
    }
    if (tid < NC) vsh[tid] = g_v[tid];
    __syncthreads();

    // ---- MMA: 2-D warp partition: wr=wid>>1 (32 rows), wc=wid&1 (64 cols) ----
    const int wr = wid >> 1;
    const int wc = wid & 1;
    float acc[16][4];
#pragma unroll
    for (int f = 0; f < 16; f++) { acc[f][0] = acc[f][1] = acc[f][2] = acc[f][3] = 0.f; }

    const uint32_t aOff0 = (uint32_t)((wr * 32 + (lane & 15)) * STRB + ((lane >> 4) << 4));
    const uint32_t aOff1 = aOff0 + 16 * STRB;
    const uint32_t bOffL =
        (uint32_t)(((lane & 7) + ((lane >> 4) << 3)) * STRB + (((lane >> 3) & 1) << 4));

#pragma unroll
    for (int k = 0; k < 4; k++) {
        uint32_t ah0[4], ah1[4], al0[4], al1[4];
        ldsm_x4(ah0, sb + SM_AHI + aOff0 + k * 32);
        ldsm_x4(ah1, sb + SM_AHI + aOff1 + k * 32);
        ldsm_x4(al0, sb + SM_ALO + aOff0 + k * 32);
        ldsm_x4(al1, sb + SM_ALO + aOff1 + k * 32);
#pragma unroll
        for (int nb = 0; nb < 4; nb++) {
            const uint32_t bRow = (uint32_t)((wc * 64 + nb * 16) * STRB) + bOffL + k * 32;
            uint32_t bh[4], bl[4];
            ldsm_x4(bh, sb + SM_BHI + bRow);
            mma16816(acc[nb * 2 + 0], ah0, bh[0], bh[1]);
            mma16816(acc[nb * 2 + 1], ah0, bh[2], bh[3]);
            mma16816(acc[8 + nb * 2 + 0], ah1, bh[0], bh[1]);
            mma16816(acc[8 + nb * 2 + 1], ah1, bh[2], bh[3]);
            mma16816(acc[nb * 2 + 0], al0, bh[0], bh[1]);
            mma16816(acc[nb * 2 + 1], al0, bh[2], bh[3]);
            mma16816(acc[8 + nb * 2 + 0], al1, bh[0], bh[1]);
            mma16816(acc[8 + nb * 2 + 1], al1, bh[2], bh[3]);
            ldsm_x4(bl, sb + SM_BLO + bRow);
            mma16816(acc[nb * 2 + 0], ah0, bl[0], bl[1]);
            mma16816(acc[nb * 2 + 1], ah0, bl[2], bl[3]);
            mma16816(acc[8 + nb * 2 + 0], ah1, bl[0], bl[1]);
            mma16816(acc[8 + nb * 2 + 1], ah1, bl[2], bl[3]);
        }
    }

    __syncthreads();  // all MMA smem reads done; safe to overlay w

    // ---- epilogue: w = D + v into smem ----
    float* wsh = (float*)(smem + SM_WSH);
    {
        const int g = lane >> 2, tig = lane & 3;
#pragma unroll
        for (int rb = 0; rb < 2; rb++) {
            const int row0 = wr * 32 + rb * 16 + g;
#pragma unroll
            for (int nb = 0; nb < 4; nb++) {
#pragma unroll
                for (int j = 0; j < 2; j++) {
                    const int col = wc * 64 + nb * 16 + j * 8 + 2 * tig;
                    const float* a = acc[rb * 8 + nb * 2 + j];
                    float v0 = vsh[col], v1 = vsh[col + 1];
                    *(float2*)&wsh[row0 * WSTRIDE + col] = make_float2(a[0] + v0, a[1] + v1);
                    *(float2*)&wsh[(row0 + 8) * WSTRIDE + col] = make_float2(a[2] + v0, a[3] + v1);
                }
            }
        }
    }
    __syncthreads();  // w fully written (rows span warps)

    // ---- score+softmax v4: warp -> 16 nodes in two groups of 8.
    //      lane = (q=node-in-group lane>>2, t=quarter lane&3).
    //      w register-resident (512B/node from smem, once).
    //      SECTOR-EFFICIENT indexing xp[4*i + t]: per LDG, lanes t=0..3 read
    //      offsets 64i+16t -> 64B contiguous (full 32B sectors). w uses the
    //      same permutation; dots are order-invariant. ----
    const int* cols = ei + E;
    const int r0 = wid * 16;
    const int q = lane >> 2;
    const int t = lane & 3;

#pragma unroll
    for (int h = 0; h < 2; h++) {
        const int r = r0 + h * 8 + q;
        const int node = rowBase + r;
        const bool active = node < n;

        // w chunks under the (4i+t) permutation; head1 at +16 float4s
        const float4* wr4 = (const float4*)(wsh + r * WSTRIDE);
        float4 w0[4], w1[4];
#pragma unroll
        for (int i = 0; i < 4; i++) {
            w0[i] = wr4[4 * i + t];
            w1[i] = wr4[16 + 4 * i + t];
        }

        int cj[8];
        if (active) {
            const int4* cp = (const int4*)(cols + (size_t)node * DEG);
            int4 ca = cp[0], cb = cp[1];
            cj[0] = ca.x; cj[1] = ca.y; cj[2] = ca.z; cj[3] = ca.w;
            cj[4] = cb.x; cj[5] = cb.y; cj[6] = cb.z; cj[7] = cb.w;
        } else {
#pragma unroll
            for (int j = 0; j < 8; j++) cj[j] = 0;
        }

        // depth-2 prefetch, sector-efficient loads
        float4 xA[4], xB[4];
        {
            const float4* xp = (const float4*)(x + (size_t)cj[0] * DM);
#pragma unroll
            for (int i = 0; i < 4; i++) xA[i] = xp[4 * i + t];
            const float4* xq = (const float4*)(x + (size_t)cj[1] * DM);
#pragma unroll
            for (int i = 0; i < 4; i++) xB[i] = xq[4 * i + t];
        }

        float s0[8], s1[8];
#pragma unroll
        for (int j = 0; j < 8; j++) {
            float4 c0, c1, c2, c3;
            if ((j & 1) == 0) { c0 = xA[0]; c1 = xA[1]; c2 = xA[2]; c3 = xA[3]; }
            else              { c0 = xB[0]; c1 = xB[1]; c2 = xB[2]; c3 = xB[3]; }
            if (j + 2 < 8) {
                const float4* xn = (const float4*)(x + (size_t)cj[j + 2] * DM);
                if ((j & 1) == 0) {
#pragma unroll
                    for (int i = 0; i < 4; i++) xA[i] = xn[4 * i + t];
                } else {
#pragma unroll
                    for (int i = 0; i < 4; i++) xB[i] = xn[4 * i + t];
                }
            }
            float p0 = (dot4(w0[0], c0) + dot4(w0[1], c1)) + (dot4(w0[2], c2) + dot4(w0[3], c3));
            float p1 = (dot4(w1[0], c0) + dot4(w1[1], c1)) + (dot4(w1[2], c2) + dot4(w1[3], c3));
            p0 += __shfl_xor_sync(FULL, p0, 1);
            p0 += __shfl_xor_sync(FULL, p0, 2);
            p1 += __shfl_xor_sync(FULL, p1, 1);
            p1 += __shfl_xor_sync(FULL, p1, 2);
            s0[j] = p0 * 8.0f;
            s1[j] = p1 * 8.0f;
        }

        // softmax in registers (all 4 lanes of the group hold identical s)
        float m0 = fmaxf(fmaxf(fmaxf(s0[0], s0[1]), fmaxf(s0[2], s0[3])),
                         fmaxf(fmaxf(s0[4], s0[5]), fmaxf(s0[6], s0[7])));
        float m1 = fmaxf(fmaxf(fmaxf(s1[0], s1[1]), fmaxf(s1[2], s1[3])),
                         fmaxf(fmaxf(s1[4], s1[5]), fmaxf(s1[6], s1[7])));
        float e0[8], e1[8];
#pragma unroll
        for (int j = 0; j < 8; j++) {
            e0[j] = __expf(s0[j] - m0);
            e1[j] = __expf(s1[j] - m1);
        }
        float z0 = (e0[0] + e0[1]) + (e0[2] + e0[3]) + (e0[4] + e0[5]) + (e0[6] + e0[7]);
        float z1 = (e1[0] + e1[1]) + (e1[2] + e1[3]) + (e1[4] + e1[5]) + (e1[6] + e1[7]);
        float i0 = 0.5f / z0, i1 = 0.5f / z1;

        // lane t writes outputs 2t, 2t+1
        float a0 = sel4(e0[0], e0[2], e0[4], e0[6], t);
        float a1 = sel4(e0[1], e0[3], e0[5], e0[7], t);
        float b0 = sel4(e1[0], e1[2], e1[4], e1[6], t);
        float b1 = sel4(e1[1], e1[3], e1[5], e1[7], t);
        if (active) {
            float2 o = make_float2(a0 * i0 + b0 * i1, a1 * i0 + b1 * i1);
            ((float2*)(out + (size_t)node * DEG))[t] = o;
        }
    }
}

// ---------------------------------------------------------------------------
extern "C" void kernel_launch(void* const* d_in, const int* in_sizes, int n_in,
                              void* d_out, int out_size) {
    const float* x = (const float*)d_in[0];
    const float* W = (const float*)d_in[1];
    const float* b = (const float*)d_in[2];
    const int* ei  = (const int*)d_in[3];
    float* out = (float*)d_out;

    const int n = in_sizes[0] / DM;
    const int E = in_sizes[3] / 2;

    static bool attr_set = false;
    if (!attr_set) {
        cudaFuncSetAttribute(fused_kernel, cudaFuncAttributeMaxDynamicSharedMemorySize, SMEM_BYTES);
        attr_set = true;
    }

    prologue_kernel<<<16, 256>>>(W, b);
    fused_kernel<<<(n + TILE - 1) / TILE, 256, SMEM_BYTES>>>(x, ei, out, n, E);
}